// round 3
// baseline (speedup 1.0000x reference)
#include <cuda_runtime.h>
#include <cstdint>

#define COLS     16384
#define KSEL     256
#define NT       1024
#define EPT      16              // elements per thread
#define CAP      2048
#define NBUF     3
#define ROWBYTES (COLS * 4)      // 65536

typedef unsigned long long u64;

// smem layout (dynamic): 3 row buffers | cand[2048] u64 | mbar[3] u64 | swarp[32] | s_cnt
#define SMEM_CAND  (NBUF * ROWBYTES)                  // 196608
#define SMEM_MBAR  (SMEM_CAND + CAP * 8)              // 212992
#define SMEM_SWARP (SMEM_MBAR + NBUF * 8)             // 213016
#define SMEM_CNT   (SMEM_SWARP + 32 * 4)              // 213144
#define SMEM_TOTAL (SMEM_CNT + 64)                    // 213208 -> fits 227KB

// monotone float->uint key: larger float => larger key
__device__ __forceinline__ unsigned f2k(float f) {
    unsigned u = __float_as_uint(f);
    return u ^ ((unsigned)((int)u >> 31) | 0x80000000u);
}
__device__ __forceinline__ float k2f(unsigned k) {
    unsigned u = (k & 0x80000000u) ? (k ^ 0x80000000u) : ~k;
    return __uint_as_float(u);
}
__device__ __forceinline__ float k2relu(unsigned k) {
    return (k > 0x80000000u) ? __uint_as_float(k ^ 0x80000000u) : 0.0f;
}
__device__ __forceinline__ unsigned smem_u32(const void* p) {
    unsigned r;
    asm("{ .reg .u64 t; cvta.to.shared.u64 t, %1; cvt.u32.u64 %0, t; }" : "=r"(r) : "l"(p));
    return r;
}
__device__ __forceinline__ void mbar_wait(unsigned mbar, unsigned phase) {
    asm volatile(
        "{\n\t.reg .pred P;\n\t"
        "W%=:\n\t"
        "mbarrier.try_wait.parity.acquire.cta.shared::cta.b64 P, [%0], %1, 0x989680;\n\t"
        "@P bra.uni D%=;\n\t"
        "bra.uni W%=;\n\t"
        "D%=:\n\t}"
        :: "r"(mbar), "r"(phase) : "memory");
}
__device__ __forceinline__ void bulk_load(unsigned sdst, const void* gsrc, unsigned bytes, unsigned mbar) {
    asm volatile("mbarrier.arrive.expect_tx.shared.b64 _, [%0], %1;" :: "r"(mbar), "r"(bytes) : "memory");
    asm volatile("cp.async.bulk.shared::cluster.global.mbarrier::complete_tx::bytes [%0], [%1], %2, [%3];"
                 :: "r"(sdst), "l"(gsrc), "r"(bytes), "r"(mbar) : "memory");
}

extern __shared__ char smem[];

__global__ void __launch_bounds__(NT, 1)
topk_kernel(const float* __restrict__ x, float* __restrict__ out, int rows, int gsz)
{
    const int tid = threadIdx.x, lane = tid & 31, wid = tid >> 5;
    u64*      cand  = (u64*)(smem + SMEM_CAND);
    unsigned* swarp = (unsigned*)(smem + SMEM_SWARP);
    unsigned* s_cnt = (unsigned*)(smem + SMEM_CNT);

    unsigned mb[NBUF];
    #pragma unroll
    for (int b = 0; b < NBUF; b++) mb[b] = smem_u32(smem + SMEM_MBAR + b * 8);

    if (tid == 0) {
        #pragma unroll
        for (int b = 0; b < NBUF; b++)
            asm volatile("mbarrier.init.shared.b64 [%0], 1;" :: "r"(mb[b]) : "memory");
    }
    __syncthreads();
    asm volatile("fence.proxy.async.shared::cta;" ::: "memory");

    const int r0 = blockIdx.x;
    if (r0 >= rows) return;
    const int nIter = (rows - r0 + gsz - 1) / gsz;

    // prologue: prefetch rows j=0,1
    if (tid == 0) {
        #pragma unroll
        for (int j = 0; j < 2; j++) {
            if (j < nIter)
                bulk_load(smem_u32(smem + j * ROWBYTES),
                          x + (size_t)(r0 + (size_t)j * gsz) * COLS, ROWBYTES, mb[j]);
        }
    }

    unsigned ph0 = 0, ph1 = 0, ph2 = 0;

    for (int j = 0; j < nIter; j++) {
        const int b = j % NBUF;
        const size_t row = r0 + (size_t)j * gsz;
        float*  buf  = (float*)(smem + b * ROWBYTES);
        float4* buf4 = (float4*)buf;

        // ---- wait for this row's bulk load ----
        unsigned myph = (b == 0) ? ph0 : (b == 1) ? ph1 : ph2;
        mbar_wait(mb[b], myph);
        if (b == 0) ph0 ^= 1; else if (b == 1) ph1 ^= 1; else ph2 ^= 1;

        // ---- pull 16 elements into registers (LDS.128 x4) ----
        float w[EPT];
        #pragma unroll
        for (int i = 0; i < 4; i++) {
            float4 v = buf4[tid + i * NT];
            w[4*i] = v.x; w[4*i+1] = v.y; w[4*i+2] = v.z; w[4*i+3] = v.w;
        }

        // ---- adaptive-threshold scan-compact (zero atomics) ----
        unsigned kT = f2k(1.9f);          // ~470 expected candidates for N(0,1)
        float Tf = 1.9f;
        unsigned C = 0, base = 0, myc = 0;
        unsigned aLo = 0u, bHi = 0xFFFFFFFFu;
        for (int att = 0; att < 34; att++) {
            unsigned c = 0;
            #pragma unroll
            for (int e = 0; e < EPT; e++) c += (w[e] >= Tf);
            unsigned sc = c;                        // warp inclusive scan
            #pragma unroll
            for (int d = 1; d < 32; d <<= 1) {
                unsigned n = __shfl_up_sync(0xFFFFFFFFu, sc, d);
                if (lane >= d) sc += n;
            }
            if (lane == 31) swarp[wid] = sc;
            __syncthreads();
            if (wid == 0) {                         // cross-warp exclusive scan
                unsigned t = swarp[lane], ts = t;
                #pragma unroll
                for (int d = 1; d < 32; d <<= 1) {
                    unsigned n = __shfl_up_sync(0xFFFFFFFFu, ts, d);
                    if (lane >= d) ts += n;
                }
                swarp[lane] = ts - t;
                if (lane == 31) *s_cnt = ts;
            }
            __syncthreads();
            C = *s_cnt;
            myc = c;
            base = swarp[wid] + (sc - c);
            if (C >= KSEL && C <= CAP) break;       // normal path: first attempt
            if (C > CAP) aLo = kT; else bHi = kT;   // rare binary-search fallback
            unsigned nkT = aLo + ((bHi - aLo) >> 1);
            if (nkT == kT) break;
            kT = nkT; Tf = k2f(kT);
            __syncthreads();
        }
        // push candidates at deterministic offsets
        if (myc) {
            unsigned p = base;
            #pragma unroll
            for (int e = 0; e < EPT; e++) {
                if (w[e] >= Tf) {
                    unsigned idx = 4u * (unsigned)(tid + (e >> 2) * NT) + (e & 3);
                    if (p < CAP) cand[p] = ((u64)f2k(w[e]) << 32) | (unsigned)~idx;
                    p++;
                }
            }
        }
        __syncthreads();

        const unsigned Cw   = (C > CAP) ? CAP : C;
        const unsigned need = (KSEL < Cw) ? KSEL : Cw;

        // ---- direct exact stable rank over candidates (broadcast LDS) ----
        unsigned widx[2]; float wval[2]; int nw = 0;
        for (unsigned p = tid; p < Cw; p += NT) {
            u64 mine = cand[p];
            unsigned rk = 0;
            unsigned q = 0;
            for (; q + 4 <= Cw; q += 4) {
                rk += (cand[q]   > mine);
                rk += (cand[q+1] > mine);
                rk += (cand[q+2] > mine);
                rk += (cand[q+3] > mine);
            }
            for (; q < Cw; q++) rk += (cand[q] > mine);
            if (rk < need) {                 // higher key first, lower idx on ties
                widx[nw] = ~(unsigned)mine;
                wval[nw] = k2relu((unsigned)(mine >> 32));
                nw++;
            }
        }

        // ---- build output row in place: zero + scatter winners ----
        float4 z = make_float4(0.f, 0.f, 0.f, 0.f);
        #pragma unroll
        for (int i = 0; i < 4; i++) buf4[tid + i * NT] = z;
        __syncthreads();
        for (int q = 0; q < nw; q++) buf[widx[q]] = wval[q];
        __syncthreads();
        asm volatile("fence.proxy.async.shared::cta;" ::: "memory");

        // ---- bulk store + prefetch row j+2 ----
        if (tid == 0) {
            unsigned ssrc = smem_u32(buf);
            float* dst = out + row * COLS;
            asm volatile("cp.async.bulk.global.shared::cta.bulk_group [%0], [%1], %2;"
                         :: "l"(dst), "r"(ssrc), "n"(ROWBYTES) : "memory");
            asm volatile("cp.async.bulk.commit_group;" ::: "memory");
            if (j + 2 < nIter) {
                // ensure store of row j-1 (same buffer) has finished reading smem
                asm volatile("cp.async.bulk.wait_group.read 1;" ::: "memory");
                int b2 = (j + 2) % NBUF;
                bulk_load(smem_u32(smem + b2 * ROWBYTES),
                          x + (size_t)(r0 + (size_t)(j + 2) * gsz) * COLS, ROWBYTES, mb[b2]);
            }
        }
        // no trailing sync needed: next iteration begins with an mbarrier wait
    }

    if (tid == 0)
        asm volatile("cp.async.bulk.wait_group 0;" ::: "memory");
}

extern "C" void kernel_launch(void* const* d_in, const int* in_sizes, int n_in,
                              void* d_out, int out_size) {
    const float* x = (const float*)d_in[0];
    float* out = (float*)d_out;
    int rows = in_sizes[0] / COLS;

    int dev = 0, sms = 0;
    cudaGetDevice(&dev);
    cudaDeviceGetAttribute(&sms, cudaDevAttrMultiProcessorCount, dev);
    if (sms <= 0) sms = 148;
    if (sms > rows) sms = rows;

    cudaFuncSetAttribute(topk_kernel, cudaFuncAttributeMaxDynamicSharedMemorySize, SMEM_TOTAL);
    topk_kernel<<<sms, NT, SMEM_TOTAL>>>(x, out, rows, sms);
}

// round 4
// speedup vs baseline: 2.1965x; 2.1965x over previous
#include <cuda_runtime.h>
#include <cstdint>

#define COLS 16384
#define KSEL 256
#define NT   512
#define VPT  8            // float4 per thread
#define CAP  2048
#define WCAP 256          // boundary-window list capacity

typedef unsigned long long u64;

__device__ __forceinline__ unsigned f2k(float f) {
    unsigned u = __float_as_uint(f);
    return u ^ ((unsigned)((int)u >> 31) | 0x80000000u);
}
__device__ __forceinline__ float k2f(unsigned k) {
    unsigned u = (k & 0x80000000u) ? (k ^ 0x80000000u) : ~k;
    return __uint_as_float(u);
}
__device__ __forceinline__ float k2relu(unsigned k) {
    return (k > 0x80000000u) ? __uint_as_float(k ^ 0x80000000u) : 0.0f;
}

__global__ void __launch_bounds__(NT, 2)
topk_kernel(const float* __restrict__ x, float* __restrict__ out)
{
    __shared__ u64 cand[CAP];
    __shared__ u64 slist[WCAP];
    __shared__ unsigned hist[256], Sarr[256], swarp[8];
    __shared__ unsigned s_cnt, s_kmax, s_j, s_above, s_m;

    const int tid  = threadIdx.x;
    const int lane = tid & 31;
    const size_t row = blockIdx.x;
    const float4* __restrict__ xr4   = reinterpret_cast<const float4*>(x + row * COLS);
    float*        __restrict__ orow  = out + row * COLS;
    float4*       __restrict__ orow4 = reinterpret_cast<float4*>(orow);

    if (tid == 0) { s_cnt = 0; s_kmax = 0; s_m = 0; }

    // ---- 1) front-batch all loads (MLP=8/warp); zero-fill overlaps latency ----
    float4 v[VPT];
    #pragma unroll
    for (int i = 0; i < VPT; i++) v[i] = xr4[tid + i * NT];
    float4 z = make_float4(0.f, 0.f, 0.f, 0.f);
    #pragma unroll
    for (int i = 0; i < VPT; i++) orow4[tid + i * NT] = z;
    __syncthreads();

    // ---- 2) row max (for histogram span) ----
    float fm = v[0].x;
    #pragma unroll
    for (int i = 0; i < VPT; i++) {
        float4 w = v[i];
        fm = fmaxf(fm, fmaxf(fmaxf(w.x, w.y), fmaxf(w.z, w.w)));
    }
    #pragma unroll
    for (int off = 16; off; off >>= 1)
        fm = fmaxf(fm, __shfl_down_sync(0xFFFFFFFFu, fm, off));
    if (lane == 0) atomicMax(&s_kmax, f2k(fm));

    // ---- 3) candidate push (uniform-address atomic, REDUX-aggregated) ----
    unsigned kT = f2k(1.9f);              // ~470 expected candidates for N(0,1)
    float Tf = 1.9f;
    unsigned C = 0;
    unsigned aLo = 0u, bHi = 0xFFFFFFFFu;
    for (int att = 0; att < 34; att++) {
        #pragma unroll
        for (int i = 0; i < VPT; i++) {
            float4 w = v[i];
            unsigned idx0 = 4u * (unsigned)(tid + i * NT);
            if (w.x >= Tf) { unsigned p = atomicAdd(&s_cnt, 1u); if (p < CAP) cand[p] = ((u64)f2k(w.x) << 32) | (unsigned)~(idx0);      }
            if (w.y >= Tf) { unsigned p = atomicAdd(&s_cnt, 1u); if (p < CAP) cand[p] = ((u64)f2k(w.y) << 32) | (unsigned)~(idx0 + 1u); }
            if (w.z >= Tf) { unsigned p = atomicAdd(&s_cnt, 1u); if (p < CAP) cand[p] = ((u64)f2k(w.z) << 32) | (unsigned)~(idx0 + 2u); }
            if (w.w >= Tf) { unsigned p = atomicAdd(&s_cnt, 1u); if (p < CAP) cand[p] = ((u64)f2k(w.w) << 32) | (unsigned)~(idx0 + 3u); }
        }
        __syncthreads();
        C = s_cnt;
        if (C >= KSEL && C <= CAP) break;        // normal path: first attempt
        if (C > CAP) aLo = kT; else bHi = kT;    // rare binary-search fallback
        unsigned nkT = aLo + ((bHi - aLo) >> 1);
        if (nkT == kT) break;
        kT = nkT; Tf = k2f(kT);
        __syncthreads();
        if (tid == 0) s_cnt = 0;
        __syncthreads();
    }
    if (C > CAP) C = CAP;
    unsigned kmax = s_kmax;
    unsigned need = (KSEL < C) ? KSEL : C;

    unsigned winLo = kT;
    unsigned span  = kmax + 1u - kT;      // >=1 when C>=1
    int sh = (span > 1u) ? (32 - __clz(span - 1u) - 8) : 0;
    if (sh < 0) sh = 0;
    unsigned W = 1u << sh;

    // ---- 4) 256-bin histogram narrowing (typically ONE round) ----
    if (C > 0) {
        for (int r = 0; r < 4; r++) {
            if (tid < 256) hist[tid] = 0;
            __syncthreads();
            for (unsigned p = tid; p < C; p += NT) {
                unsigned k = (unsigned)(cand[p] >> 32);
                unsigned d = k - winLo;
                if ((d >> sh) < 256u) atomicAdd(&hist[d >> sh], 1u);
            }
            __syncthreads();
            // suffix sums Sarr[t] = sum_{j>=t} hist[j]
            unsigned s = 0;
            if (tid < 256) {
                s = hist[tid];
                #pragma unroll
                for (int d = 1; d < 32; d <<= 1) {
                    unsigned n = __shfl_down_sync(0xFFFFFFFFu, s, d);
                    if (lane + d < 32) s += n;
                }
                if (lane == 0) swarp[tid >> 5] = s;   // warp suffix total
            }
            __syncthreads();
            if (tid < 256) {
                unsigned add = 0;
                int w = tid >> 5;
                #pragma unroll
                for (int ww = 0; ww < 8; ww++) if (ww > w) add += swarp[ww];
                // recover this lane's suffix within warp: s currently holds
                // sum over lanes [lane..31]; that is exactly what we need
                Sarr[tid] = s + add;
            }
            __syncthreads();
            if (tid < 256) {
                unsigned Sv = Sarr[tid];
                unsigned Sn = (tid == 255) ? 0u : Sarr[tid + 1];
                if (Sv >= need && Sn < need) { s_j = tid; s_above = Sn; }
            }
            __syncthreads();
            unsigned j = s_j, nab = s_above;
            winLo += j << sh;
            need  -= nab;
            W = 1u << sh;
            unsigned cnt_in = Sarr[j] - nab;
            if (cnt_in <= 32u || sh == 0) break;
            sh = (sh >= 8) ? sh - 8 : 0;
            __syncthreads();   // Sarr reads done before next round rewrites
        }

        // ---- 5) single final pass: write sure winners, gather boundary window ----
        u64 fHi = (u64)winLo + (u64)W;
        for (unsigned p = tid; p < C; p += NT) {
            u64 ck = cand[p];
            unsigned k = (unsigned)(ck >> 32);
            if ((u64)k >= fHi) {
                orow[~(unsigned)ck] = k2relu(k);
            } else if (k >= winLo) {
                unsigned q = atomicAdd(&s_m, 1u);
                if (q < WCAP) slist[q] = ck;
            }
        }
        __syncthreads();
        unsigned m = s_m; if (m > WCAP) m = WCAP;

        // exact stable rank on the tiny window (higher key, then lower index)
        for (unsigned p = tid; p < m; p += NT) {
            u64 mine = slist[p];
            unsigned rk = 0;
            for (unsigned q = 0; q < m; q++) rk += (slist[q] > mine);
            if (rk < need) {
                orow[~(unsigned)mine] = k2relu((unsigned)(mine >> 32));
            }
        }
    }
}

extern "C" void kernel_launch(void* const* d_in, const int* in_sizes, int n_in,
                              void* d_out, int out_size) {
    const float* x = (const float*)d_in[0];
    float* out = (float*)d_out;
    int rows = in_sizes[0] / COLS;
    topk_kernel<<<rows, NT>>>(x, out);
}

// round 5
// speedup vs baseline: 2.3665x; 1.0774x over previous
#include <cuda_runtime.h>
#include <cstdint>

#define COLS 16384
#define KSEL 256
#define NT   512
#define EPT  32           // elements per thread (8 x float4)
#define CAP  2048
#define WCAP 256          // boundary-window list capacity

typedef unsigned long long u64;

__device__ __forceinline__ unsigned f2k(float f) {
    unsigned u = __float_as_uint(f);
    return u ^ ((unsigned)((int)u >> 31) | 0x80000000u);
}
__device__ __forceinline__ float k2f(unsigned k) {
    unsigned u = (k & 0x80000000u) ? (k ^ 0x80000000u) : ~k;
    return __uint_as_float(u);
}
__device__ __forceinline__ float k2relu(unsigned k) {
    return (k > 0x80000000u) ? __uint_as_float(k ^ 0x80000000u) : 0.0f;
}

__global__ void __launch_bounds__(NT, 2)
topk_kernel(const float* __restrict__ x, float* __restrict__ out)
{
    __shared__ u64 cand[CAP];
    __shared__ u64 slist[WCAP];
    __shared__ unsigned hist[256], Sarr[256], swarp[8];
    __shared__ unsigned s_cnt, s_kmax, s_j, s_above, s_m;

    const int tid  = threadIdx.x;
    const int lane = tid & 31;
    const size_t row = blockIdx.x;
    const float4* __restrict__ xr4   = reinterpret_cast<const float4*>(x + row * COLS);
    float*        __restrict__ orow  = out + row * COLS;
    float4*       __restrict__ orow4 = reinterpret_cast<float4*>(orow);

    if (tid == 0) { s_cnt = 0; s_kmax = 0; s_m = 0; }

    // ---- 1) front-batch all loads (MLP=8/warp); zero-fill overlaps latency ----
    float w[EPT];
    #pragma unroll
    for (int i = 0; i < 8; i++) {
        float4 t = xr4[tid + i * NT];
        w[4*i] = t.x; w[4*i+1] = t.y; w[4*i+2] = t.z; w[4*i+3] = t.w;
    }
    float4 z = make_float4(0.f, 0.f, 0.f, 0.f);
    #pragma unroll
    for (int i = 0; i < 8; i++) orow4[tid + i * NT] = z;
    __syncthreads();   // s_cnt/s_kmax/s_m ready

    // ---- 2) row max (histogram span) ----
    float fm = w[0];
    #pragma unroll
    for (int e = 1; e < EPT; e++) fm = fmaxf(fm, w[e]);
    #pragma unroll
    for (int off = 16; off; off >>= 1)
        fm = fmaxf(fm, __shfl_down_sync(0xFFFFFFFFu, fm, off));
    if (lane == 0) atomicMax(&s_kmax, f2k(fm));

    // ---- 3) scan-based candidate push: ONE atomic per warp per attempt ----
    unsigned kT = f2k(1.9f);              // ~470 expected candidates for N(0,1)
    float Tf = 1.9f;
    unsigned C = 0;
    unsigned aLo = 0u, bHi = 0xFFFFFFFFu;
    for (int att = 0; att < 34; att++) {
        unsigned c = 0;
        #pragma unroll
        for (int e = 0; e < EPT; e++) c += (w[e] >= Tf);

        unsigned sc = c;                  // warp inclusive scan
        #pragma unroll
        for (int d = 1; d < 32; d <<= 1) {
            unsigned n = __shfl_up_sync(0xFFFFFFFFu, sc, d);
            if (lane >= d) sc += n;
        }
        unsigned wtot = __shfl_sync(0xFFFFFFFFu, sc, 31);
        unsigned base = 0;
        if (lane == 0 && wtot) base = atomicAdd(&s_cnt, wtot);
        base = __shfl_sync(0xFFFFFFFFu, base, 0);

        unsigned p = base + (sc - c);     // this thread's deterministic slot
        if (c) {
            #pragma unroll
            for (int e = 0; e < EPT; e++) {
                if (w[e] >= Tf) {
                    unsigned idx = 4u * (unsigned)(tid + (e >> 2) * NT) + (e & 3);
                    if (p < CAP) cand[p] = ((u64)f2k(w[e]) << 32) | (unsigned)~idx;
                    p++;
                }
            }
        }
        __syncthreads();
        C = s_cnt;
        if (C >= KSEL && C <= CAP) break;        // normal path: first attempt
        if (C > CAP) aLo = kT; else bHi = kT;    // rare binary-search fallback
        unsigned nkT = aLo + ((bHi - aLo) >> 1);
        if (nkT == kT) break;
        kT = nkT; Tf = k2f(kT);
        __syncthreads();
        if (tid == 0) s_cnt = 0;
        __syncthreads();
    }
    if (C > CAP) C = CAP;
    unsigned kmax = s_kmax;
    unsigned need = (KSEL < C) ? KSEL : C;

    unsigned winLo = kT;
    unsigned span  = kmax + 1u - kT;
    int sh = (span > 1u) ? (32 - __clz(span - 1u) - 8) : 0;
    if (sh < 0) sh = 0;
    unsigned W = 1u << sh;

    // ---- 4) 256-bin histogram narrowing (typically ONE round) ----
    if (C > 0) {
        for (int r = 0; r < 4; r++) {
            if (tid < 256) hist[tid] = 0;
            __syncthreads();
            for (unsigned p = tid; p < C; p += NT) {
                unsigned k = (unsigned)(cand[p] >> 32);
                unsigned d = k - winLo;
                if ((d >> sh) < 256u) atomicAdd(&hist[d >> sh], 1u);
            }
            __syncthreads();
            // suffix sums Sarr[t] = sum_{j>=t} hist[j]
            unsigned s = 0;
            if (tid < 256) {
                s = hist[tid];
                #pragma unroll
                for (int d = 1; d < 32; d <<= 1) {
                    unsigned n = __shfl_down_sync(0xFFFFFFFFu, s, d);
                    if (lane + d < 32) s += n;
                }
                if (lane == 0) swarp[tid >> 5] = s;
            }
            __syncthreads();
            if (tid < 256) {
                unsigned add = 0;
                int wd = tid >> 5;
                #pragma unroll
                for (int ww = 0; ww < 8; ww++) if (ww > wd) add += swarp[ww];
                Sarr[tid] = s + add;
            }
            __syncthreads();
            if (tid < 256) {
                unsigned Sv = Sarr[tid];
                unsigned Sn = (tid == 255) ? 0u : Sarr[tid + 1];
                if (Sv >= need && Sn < need) { s_j = tid; s_above = Sn; }
            }
            __syncthreads();
            unsigned j = s_j, nab = s_above;
            winLo += j << sh;
            need  -= nab;
            W = 1u << sh;
            unsigned cnt_in = Sarr[j] - nab;
            if (cnt_in <= 32u || sh == 0) break;
            sh = (sh >= 8) ? sh - 8 : 0;
            __syncthreads();   // Sarr reads done before next round rewrites
        }

        // ---- 5) single final pass: write sure winners, gather boundary window ----
        u64 fHi = (u64)winLo + (u64)W;
        for (unsigned p = tid; p < C; p += NT) {
            u64 ck = cand[p];
            unsigned k = (unsigned)(ck >> 32);
            if ((u64)k >= fHi) {
                orow[~(unsigned)ck] = k2relu(k);
            } else if (k >= winLo) {
                unsigned q = atomicAdd(&s_m, 1u);
                if (q < WCAP) slist[q] = ck;
            }
        }
        __syncthreads();
        unsigned m = s_m; if (m > WCAP) m = WCAP;

        // exact stable rank on the tiny window (higher key, then lower index)
        for (unsigned p = tid; p < m; p += NT) {
            u64 mine = slist[p];
            unsigned rk = 0;
            for (unsigned q = 0; q < m; q++) rk += (slist[q] > mine);
            if (rk < need) {
                orow[~(unsigned)mine] = k2relu((unsigned)(mine >> 32));
            }
        }
    }
}

extern "C" void kernel_launch(void* const* d_in, const int* in_sizes, int n_in,
                              void* d_out, int out_size) {
    const float* x = (const float*)d_in[0];
    float* out = (float*)d_out;
    int rows = in_sizes[0] / COLS;
    topk_kernel<<<rows, NT>>>(x, out);
}